// round 15
// baseline (speedup 1.0000x reference)
#include <cuda_runtime.h>
#include <cuda_fp16.h>
#include <cstddef>
#include <cstdint>

// ---------------------------------------------------------------------------
// MultiHeadAttention: B=2, S=2048, DIM=1024, H=16, Dh=64, fp32.
// Outputs: out [2,2048,1024] then attn [2,16,2048,2048] (flattened tuple).
//
// R15: chain-shortening on R14.
//  - Q projection output pre-scaled by log2e/8 -> scores arrive ready for ex2
//    (removes 268M FMULs and a dependency link in both sweeps).
//  - AV MMA consumes raw ex2 output (un-normalized fp16 p_u); avacc is
//    normalized once at the epilogue. attn store path keeps fp32 x inv.
// ---------------------------------------------------------------------------

#define BB 2
#define SS 2048
#define DIM 1024
#define NH 16
#define DH 64
#define ROWS_TOT (BB*SS)          // 4096

// exp(s/8) = 2^(s * 0.125 * log2 e); folded into Q at projection time
#define EXP_C 0.18033688011112042f

__device__ __forceinline__ uint32_t smem_to_u32(const void* p) {
    uint32_t a;
    asm("{ .reg .u64 t; cvta.to.shared.u64 t, %1; cvt.u32.u64 %0, t; }" : "=r"(a) : "l"(p));
    return a;
}

#define CP_ASYNC16(dst_u32, src_ptr) \
    asm volatile("cp.async.cg.shared.global [%0], [%1], 16;" \
                 :: "r"(dst_u32), "l"(src_ptr))
#define CP_COMMIT() asm volatile("cp.async.commit_group;" ::: "memory")
#define CP_WAIT1()  asm volatile("cp.async.wait_group 1;" ::: "memory")
#define CP_WAIT0()  asm volatile("cp.async.wait_group 0;" ::: "memory")

__device__ __forceinline__ void ldsm4(uint32_t* r, uint32_t addr) {
    asm volatile("ldmatrix.sync.aligned.m8n8.x4.shared.b16 {%0,%1,%2,%3}, [%4];"
        : "=r"(r[0]), "=r"(r[1]), "=r"(r[2]), "=r"(r[3]) : "r"(addr));
}
__device__ __forceinline__ void ldsm4t(uint32_t* r, uint32_t addr) {
    asm volatile("ldmatrix.sync.aligned.m8n8.x4.trans.shared.b16 {%0,%1,%2,%3}, [%4];"
        : "=r"(r[0]), "=r"(r[1]), "=r"(r[2]), "=r"(r[3]) : "r"(addr));
}
__device__ __forceinline__ void mma16816(float* c, const uint32_t* a, const uint32_t* b) {
    asm volatile("mma.sync.aligned.m16n8k16.row.col.f32.f16.f16.f32 "
        "{%0,%1,%2,%3}, {%4,%5,%6,%7}, {%8,%9}, {%0,%1,%2,%3};"
        : "+f"(c[0]), "+f"(c[1]), "+f"(c[2]), "+f"(c[3])
        : "r"(a[0]), "r"(a[1]), "r"(a[2]), "r"(a[3]), "r"(b[0]), "r"(b[1]));
}
__device__ __forceinline__ uint32_t pack2h(float a, float b) {
    __half2 t = __floats2half2_rn(a, b);
    return *(uint32_t*)&t;
}
// two exp2 in one MUFU op
__device__ __forceinline__ uint32_t h2ex2(uint32_t x) {
    uint32_t r;
    asm("ex2.approx.f16x2 %0, %1;" : "=r"(r) : "r"(x));
    return r;
}
__device__ __forceinline__ float2 h2f2(uint32_t h) {
    return __half22float2(*(__half2*)&h);
}
__device__ __forceinline__ void stg_cs_v2(float* p, float x, float y) {
    asm volatile("st.global.cs.v2.f32 [%0], {%1, %2};" :: "l"(p), "f"(x), "f"(y) : "memory");
}

// ---------------- scratch (device globals) ----------------------------------
__device__ float g_dummy[ROWS_TOT * DIM];
__device__ __half g_act[3 * ROWS_TOT * DIM];
__device__ __half g_w[4 * DIM * DIM];
__device__ __half g_qh[ROWS_TOT * DIM];
__device__ __half g_kh[ROWS_TOT * DIM];
__device__ __half g_vh[ROWS_TOT * DIM];
__device__ __half g_rh[ROWS_TOT * DIM];

// ---------------------------------------------------------------------------
// batched fp32 -> fp16 converters
// ---------------------------------------------------------------------------
__global__ __launch_bounds__(256)
void cvt3(const float* __restrict__ s0, const float* __restrict__ s1,
          const float* __restrict__ s2, __half* __restrict__ dst, int n4)
{
    int i = blockIdx.x * blockDim.x + threadIdx.x;
    if (i >= n4) return;
    int z = blockIdx.z;
    const float* src = (z == 0) ? s0 : (z == 1) ? s1 : s2;
    __half* d = dst + (size_t)z * n4 * 4;
    float4 v = ((const float4*)src)[i];
    ((uint32_t*)d)[2 * i]     = pack2h(v.x, v.y);
    ((uint32_t*)d)[2 * i + 1] = pack2h(v.z, v.w);
}

__global__ __launch_bounds__(256)
void cvt4(const float* __restrict__ s0, const float* __restrict__ s1,
          const float* __restrict__ s2, const float* __restrict__ s3,
          __half* __restrict__ dst, int n4)
{
    int i = blockIdx.x * blockDim.x + threadIdx.x;
    if (i >= n4) return;
    int z = blockIdx.z;
    const float* src = (z == 0) ? s0 : (z == 1) ? s1 : (z == 2) ? s2 : s3;
    __half* d = dst + (size_t)z * n4 * 4;
    float4 v = ((const float4*)src)[i];
    ((uint32_t*)d)[2 * i]     = pack2h(v.x, v.y);
    ((uint32_t*)d)[2 * i + 1] = pack2h(v.z, v.w);
}

// ---------------------------------------------------------------------------
// fp16 HMMA GEMM core; epilogue scaled by cscale (used to pre-scale Q).
// ---------------------------------------------------------------------------
#define KC 64
#define PLANE 16384
#define TCBUF (2 * PLANE)
#define TC_SMEM_BYTES (2 * TCBUF)     // 65536

struct QkvArgs {
    const float* bias[3];
    __half* C[3];
};

__device__ __forceinline__ void gemm_body(
    const __half* __restrict__ A, const __half* __restrict__ W,
    const float* __restrict__ bias, float cscale, float* __restrict__ Cf,
    __half* __restrict__ Ch, int M, int N, int K, char* smem)
{
    uint32_t sb = smem_to_u32(smem);
    int tid = threadIdx.x;
    int warp = tid >> 5, lane = tid & 31;
    int n0 = blockIdx.x * 128;
    int m0 = blockIdx.y * 128;
    int wm = warp & 1, wn = warp >> 1;

    const __half* srcs[2] = { A + (size_t)m0 * K, W + (size_t)n0 * K };
    int lr = tid >> 3, lg = tid & 7;

    auto issue = [&](int c, int buf) {
        uint32_t bufb = sb + buf * TCBUF;
#pragma unroll
        for (int op = 0; op < 2; op++) {
            const __half* s = srcs[op] + c * KC;
            uint32_t pb = bufb + op * PLANE;
#pragma unroll
            for (int l = 0; l < 4; l++) {
                int r = lr + l * 32;
                uint32_t d = pb + r * 128 + ((lg ^ (r & 7)) << 4);
                CP_ASYNC16(d, s + (size_t)r * K + lg * 8);
            }
        }
        CP_COMMIT();
    };

    float acc[16][4];
#pragma unroll
    for (int i = 0; i < 16; i++)
#pragma unroll
        for (int j = 0; j < 4; j++) acc[i][j] = 0.f;

    int nch = K / KC;
    issue(0, 0);
    int r8 = lane & 7, grp = lane >> 3;

    for (int ch = 0; ch < nch; ch++) {
        int buf = ch & 1;
        if (ch + 1 < nch) { issue(ch + 1, buf ^ 1); CP_WAIT1(); }
        else              { CP_WAIT0(); }
        __syncthreads();

        uint32_t Ap = sb + buf * TCBUF;
        uint32_t Bp = Ap + PLANE;

#pragma unroll
        for (int ks = 0; ks < 4; ks++) {
            int c0 = ks * 2;
            uint32_t af[4][4], bf[8];
#pragma unroll
            for (int mf = 0; mf < 4; mf++) {
                int row = wm * 64 + mf * 16 + (grp & 1) * 8 + r8;
                int ck = c0 + (grp >> 1);
                uint32_t off = row * 128 + ((ck ^ (row & 7)) << 4);
                ldsm4(af[mf], Ap + off);
            }
#pragma unroll
            for (int p = 0; p < 2; p++) {
                int row = wn * 32 + p * 16 + (grp >> 1) * 8 + r8;
                int ck = c0 + (grp & 1);
                uint32_t off = row * 128 + ((ck ^ (row & 7)) << 4);
                ldsm4(&bf[p * 4], Bp + off);
            }
#pragma unroll
            for (int mf = 0; mf < 4; mf++)
#pragma unroll
                for (int nf = 0; nf < 4; nf++)
                    mma16816(acc[mf * 4 + nf], af[mf], &bf[nf * 2]);
        }
        __syncthreads();
    }

    int erow = lane >> 2, ecol = (lane & 3) * 2;
#pragma unroll
    for (int mf = 0; mf < 4; mf++) {
#pragma unroll
        for (int nf = 0; nf < 4; nf++) {
            float* cc = acc[mf * 4 + nf];
            int gm = m0 + wm * 64 + mf * 16 + erow;
            int gn = n0 + wn * 32 + nf * 8 + ecol;
            float2 b2 = *(const float2*)(bias + gn);
            float f0 = (cc[0] + b2.x) * cscale, f1 = (cc[1] + b2.y) * cscale;
            float f2 = (cc[2] + b2.x) * cscale, f3 = (cc[3] + b2.y) * cscale;
            if (Cf) {
                *(float2*)(Cf + (size_t)gm * N + gn)       = make_float2(f0, f1);
                *(float2*)(Cf + (size_t)(gm + 8) * N + gn) = make_float2(f2, f3);
            } else {
                *(uint32_t*)(Ch + (size_t)gm * N + gn)       = pack2h(f0, f1);
                *(uint32_t*)(Ch + (size_t)(gm + 8) * N + gn) = pack2h(f2, f3);
            }
        }
    }
}

__global__ __launch_bounds__(256)
void tc_gemm_qkv(const __half* __restrict__ act, const __half* __restrict__ w,
                 QkvArgs args, int M, int N, int K)
{
    extern __shared__ __align__(1024) char smem[];
    int z = blockIdx.z;
    float cs = (z == 0) ? EXP_C : 1.f;   // pre-scale Q for ex2
    gemm_body(act + (size_t)z * ROWS_TOT * DIM, w + (size_t)z * DIM * DIM,
              args.bias[z], cs, nullptr, args.C[z], M, N, K, smem);
}

__global__ __launch_bounds__(256)
void tc_gemm_out(const __half* __restrict__ A, const __half* __restrict__ W,
                 const float* __restrict__ bias, float* __restrict__ Cf,
                 int M, int N, int K)
{
    extern __shared__ __align__(1024) char smem[];
    gemm_body(A, W, bias, 1.f, Cf, nullptr, M, N, K, smem);
}

// ---------------------------------------------------------------------------
// attn_fused: CTA = (64 q-rows, bh), 128 threads = 4 warps = 2 qg x 2 nh.
// Warp (qg, nh): q rows [qg*32,+32) (2 mf), n/k cols [nh*64,+64). 2 CTAs/SM.
// Scores arrive pre-scaled (Q * log2e/8): ex2 directly on sc.
// sweep1: rowsum(ex2(sc)); n-pair sums combined via smem.
// sweep2: recompute sc, pu = ex2(sc) (raw fp16) -> AV mma; store pu*inv as
//         fp32 attn (st.cs); avacc normalized at epilogue; reps -> fp16.
// smem: Q plane 8KB (sums after kt0) + 2 stages x (K16 + V16) = 72KB.
// ---------------------------------------------------------------------------
#define QROWS 64
#define FUS_SMEM (8192 + 2 * 32768)   // 73728

__global__ __launch_bounds__(128, 2)
void attn_fused(const __half* __restrict__ qh, const __half* __restrict__ kh,
                const __half* __restrict__ vh,
                float* __restrict__ attn, __half* __restrict__ reps)
{
    extern __shared__ __align__(1024) char smem[];
    uint32_t sb = smem_to_u32(smem);

    int tid = threadIdx.x;
    int warp = tid >> 5, lane = tid & 31;
    int r8 = lane & 7, grp = lane >> 3;
    int qg = warp >> 1, nh = warp & 1;
    int bh = blockIdx.y;
    int b = bh >> 4, h = bh & 15;
    int s0 = blockIdx.x * QROWS;

    const __half* qB = qh + ((size_t)(b * SS + s0)) * DIM + h * DH;
    const __half* kB = kh + ((size_t)b * SS) * DIM + h * DH;
    const __half* vB = vh + ((size_t)b * SS) * DIM + h * DH;

    int lr = tid >> 3, lg = tid & 7;   // lr 0..15

    auto load_plane128 = [&](uint32_t dst, const __half* src) {
#pragma unroll
        for (int l = 0; l < 8; l++) {
            int r = lr + l * 16;
            uint32_t d = dst + r * 128 + ((lg ^ (r & 7)) << 4);
            CP_ASYNC16(d, src + (size_t)r * DIM + lg * 8);
        }
    };
    auto load_plane64 = [&](uint32_t dst, const __half* src) {
#pragma unroll
        for (int l = 0; l < 4; l++) {
            int r = lr + l * 16;
            uint32_t d = dst + r * 128 + ((lg ^ (r & 7)) << 4);
            CP_ASYNC16(d, src + (size_t)r * DIM + lg * 8);
        }
    };
    auto issue_k = [&](int kt, int slot) {
        uint32_t stg = sb + 8192 + slot * 32768;
        load_plane128(stg, kB + (size_t)(kt * 128) * DIM);
        CP_COMMIT();
    };
    auto issue_kv = [&](int kt, int slot) {
        uint32_t stg = sb + 8192 + slot * 32768;
        load_plane128(stg, kB + (size_t)(kt * 128) * DIM);
        load_plane128(stg + 16384, vB + (size_t)(kt * 128) * DIM);
        CP_COMMIT();
    };

    load_plane64(sb, qB);              // Q plane: 64 rows
    issue_k(0, 0);
    issue_k(1, 1);

    uint32_t qf[2][4][4];              // [mf][ks]
    float sA[2] = {0.f, 0.f}, sB[2] = {0.f, 0.f};

    // score compute for one K tile: warp's 32q x 64n (scores pre-scaled)
    auto compute_scores = [&](uint32_t Kp, float sc[2][8][4]) {
#pragma unroll
        for (int mf = 0; mf < 2; mf++)
#pragma unroll
            for (int nt = 0; nt < 8; nt++)
#pragma unroll
                for (int j = 0; j < 4; j++) sc[mf][nt][j] = 0.f;
#pragma unroll
        for (int ks = 0; ks < 4; ks++) {
#pragma unroll
            for (int p = 0; p < 4; p++) {
                uint32_t bf[4];
                int gp = nh * 4 + p;
                int row = gp * 16 + (grp >> 1) * 8 + r8;
                int ck = ks * 2 + (grp & 1);
                uint32_t off = row * 128 + ((ck ^ (row & 7)) << 4);
                ldsm4(bf, Kp + off);
#pragma unroll
                for (int mf = 0; mf < 2; mf++)
#pragma unroll
                    for (int t = 0; t < 2; t++)
                        mma16816(sc[mf][2 * p + t], qf[mf][ks], &bf[t * 2]);
            }
        }
    };

    // -------- sweep 1: row sums --------
    for (int kt = 0; kt < 16; kt++) {
        if (kt == 15) { CP_WAIT0(); } else { CP_WAIT1(); }
        __syncthreads();

        if (kt == 0) {
#pragma unroll
            for (int mf = 0; mf < 2; mf++)
#pragma unroll
                for (int ks = 0; ks < 4; ks++) {
                    int row = qg * 32 + mf * 16 + (grp & 1) * 8 + r8;
                    int ck = ks * 2 + (grp >> 1);
                    uint32_t off = row * 128 + ((ck ^ (row & 7)) << 4);
                    ldsm4(qf[mf][ks], sb + off);
                }
        }

        uint32_t Kp = sb + 8192 + (kt & 1) * 32768;
        float sc[2][8][4];
        compute_scores(Kp, sc);

#pragma unroll
        for (int mf = 0; mf < 2; mf++)
#pragma unroll
            for (int nt = 0; nt < 8; nt++) {
                uint32_t pu0 = h2ex2(pack2h(sc[mf][nt][0], sc[mf][nt][1]));
                uint32_t pu1 = h2ex2(pack2h(sc[mf][nt][2], sc[mf][nt][3]));
                float2 fA = h2f2(pu0), fB = h2f2(pu1);
                sA[mf] += fA.x + fA.y;
                sB[mf] += fB.x + fB.y;
            }
        __syncthreads();
        if (kt + 2 < 16) issue_k(kt + 2, kt & 1);
    }

    // combine n-pair partial sums via smem (Q plane, dead after kt0)
    float* sums = (float*)smem;   // [64][2]
#pragma unroll
    for (int mf = 0; mf < 2; mf++) {
        sA[mf] += __shfl_xor_sync(~0u, sA[mf], 1);
        sA[mf] += __shfl_xor_sync(~0u, sA[mf], 2);
        sB[mf] += __shfl_xor_sync(~0u, sB[mf], 1);
        sB[mf] += __shfl_xor_sync(~0u, sB[mf], 2);
    }
    if ((lane & 3) == 0) {
#pragma unroll
        for (int mf = 0; mf < 2; mf++) {
            int r = qg * 32 + mf * 16 + (lane >> 2);
            sums[r * 2 + nh]       = sA[mf];
            sums[(r + 8) * 2 + nh] = sB[mf];
        }
    }
    issue_kv(0, 0);
    issue_kv(1, 1);
    __syncthreads();

    float invA[2], invB[2];
#pragma unroll
    for (int mf = 0; mf < 2; mf++) {
        int r = qg * 32 + mf * 16 + (lane >> 2);
        invA[mf] = 1.f / (sums[r * 2] + sums[r * 2 + 1]);
        invB[mf] = 1.f / (sums[(r + 8) * 2] + sums[(r + 8) * 2 + 1]);
    }

    // -------- sweep 2: attn write + AV (warp's k-half, raw-pu MMA) --------
    float avacc[2][8][4];
#pragma unroll
    for (int mf = 0; mf < 2; mf++)
#pragma unroll
        for (int i = 0; i < 8; i++)
#pragma unroll
            for (int j = 0; j < 4; j++) avacc[mf][i][j] = 0.f;

    for (int kt = 0; kt < 16; kt++) {
        if (kt == 15) { CP_WAIT0(); } else { CP_WAIT1(); }
        __syncthreads();

        uint32_t stg = sb + 8192 + (kt & 1) * 32768;
        uint32_t Kp = stg, Vp = stg + 16384;

        float sc[2][8][4];
        compute_scores(Kp, sc);

        float* a0 = attn + ((size_t)bh * SS + (s0 + qg * 32 + (lane >> 2))) * SS
                  + kt * 128 + nh * 64 + (lane & 3) * 2;
#pragma unroll
        for (int j = 0; j < 4; j++) {          // AV k16 steps in warp's 64-slice
            uint32_t Pf[2][4];
#pragma unroll
            for (int mf = 0; mf < 2; mf++) {
                float* aA = a0 + (size_t)(mf * 16) * SS;
                float* aB = aA + (size_t)8 * SS;
#pragma unroll
                for (int t = 0; t < 2; t++) {
                    int nt = 2 * j + t;
                    uint32_t pu0 = h2ex2(pack2h(sc[mf][nt][0], sc[mf][nt][1]));
                    uint32_t pu1 = h2ex2(pack2h(sc[mf][nt][2], sc[mf][nt][3]));
                    Pf[mf][t * 2]     = pu0;   // raw p_u feeds MMA directly
                    Pf[mf][t * 2 + 1] = pu1;
                    float2 fA = h2f2(pu0), fB = h2f2(pu1);
                    stg_cs_v2(aA + nt * 8, fA.x * invA[mf], fA.y * invA[mf]);
                    stg_cs_v2(aB + nt * 8, fB.x * invB[mf], fB.y * invB[mf]);
                }
            }
#pragma unroll
            for (int p = 0; p < 4; p++) {      // d16 pairs
                uint32_t vf[4];
                int srow = nh * 64 + j * 16 + (lane & 15);
                int ck = p * 2 + (lane >> 4);
                uint32_t off = srow * 128 + ((ck ^ (srow & 7)) << 4);
                ldsm4t(vf, Vp + off);
#pragma unroll
                for (int mf = 0; mf < 2; mf++)
#pragma unroll
                    for (int t = 0; t < 2; t++)
                        mma16816(avacc[mf][2 * p + t], Pf[mf], &vf[t * 2]);
            }
        }
        __syncthreads();
        if (kt + 2 < 16) issue_kv(kt + 2, kt & 1);
    }

    // -------- combine AV n-pair partials (un-normalized), scale, write reps --------
    __syncthreads();
    float* buf = (float*)(smem + 8192);   // [64][72] in dead staging area
    if (nh == 1) {
#pragma unroll
        for (int mf = 0; mf < 2; mf++)
#pragma unroll
            for (int nt = 0; nt < 8; nt++) {
                int r = qg * 32 + mf * 16 + (lane >> 2);
                int c = nt * 8 + (lane & 3) * 2;
                *(float2*)&buf[r * 72 + c] =
                    make_float2(avacc[mf][nt][0], avacc[mf][nt][1]);
                *(float2*)&buf[(r + 8) * 72 + c] =
                    make_float2(avacc[mf][nt][2], avacc[mf][nt][3]);
            }
    }
    __syncthreads();
    if (nh == 0) {
        int rowbase = b * SS + s0;
#pragma unroll
        for (int mf = 0; mf < 2; mf++)
#pragma unroll
            for (int nt = 0; nt < 8; nt++) {
                int r = qg * 32 + mf * 16 + (lane >> 2);
                int c = nt * 8 + (lane & 3) * 2;
                float2 o0 = *(float2*)&buf[r * 72 + c];
                float2 o1 = *(float2*)&buf[(r + 8) * 72 + c];
                int gn = h * DH + c;
                *(uint32_t*)(reps + (size_t)(rowbase + r) * DIM + gn) =
                    pack2h((avacc[mf][nt][0] + o0.x) * invA[mf],
                           (avacc[mf][nt][1] + o0.y) * invA[mf]);
                *(uint32_t*)(reps + (size_t)(rowbase + r + 8) * DIM + gn) =
                    pack2h((avacc[mf][nt][2] + o1.x) * invB[mf],
                           (avacc[mf][nt][3] + o1.y) * invB[mf]);
            }
    }
}

// ---------------------------------------------------------------------------
extern "C" void kernel_launch(void* const* d_in, const int* in_sizes, int n_in,
                              void* d_out, int out_size)
{
    const float* xq = (const float*)d_in[0];
    const float* xk = (const float*)d_in[1];
    const float* xv = (const float*)d_in[2];
    const float* Wq = (const float*)d_in[3];
    const float* bq = (const float*)d_in[4];
    const float* Wk = (const float*)d_in[5];
    const float* bk = (const float*)d_in[6];
    const float* Wv = (const float*)d_in[7];
    const float* bv = (const float*)d_in[8];
    const float* Wo = (const float*)d_in[9];
    const float* bo = (const float*)d_in[10];

    float* pd;
    __half *act, *w, *qh, *kh, *vh, *rh;
    cudaGetSymbolAddress((void**)&pd, g_dummy);
    cudaGetSymbolAddress((void**)&act, g_act);
    cudaGetSymbolAddress((void**)&w, g_w);
    cudaGetSymbolAddress((void**)&qh, g_qh);
    cudaGetSymbolAddress((void**)&kh, g_kh);
    cudaGetSymbolAddress((void**)&vh, g_vh);
    cudaGetSymbolAddress((void**)&rh, g_rh);

    const size_t OUT_ELEMS = (size_t)ROWS_TOT * DIM;
    const size_t ATT_ELEMS = (size_t)BB * NH * SS * SS;

    float* out_ptr = (float*)d_out;
    float* attn_ptr = (float*)d_out + OUT_ELEMS;
    size_t osz = (size_t)out_size;
    if (osz == ATT_ELEMS) {
        attn_ptr = (float*)d_out;
        out_ptr = pd;
    }

    cudaFuncSetAttribute(tc_gemm_qkv, cudaFuncAttributeMaxDynamicSharedMemorySize,
                         TC_SMEM_BYTES);
    cudaFuncSetAttribute(tc_gemm_out, cudaFuncAttributeMaxDynamicSharedMemorySize,
                         TC_SMEM_BYTES);
    cudaFuncSetAttribute(attn_fused, cudaFuncAttributeMaxDynamicSharedMemorySize,
                         FUS_SMEM);

    const int ACT4 = ROWS_TOT * DIM / 4;
    const int W4   = DIM * DIM / 4;

    cvt3<<<dim3((ACT4 + 255) / 256, 1, 3), 256>>>(xq, xk, xv, act, ACT4);
    cvt4<<<dim3((W4 + 255) / 256, 1, 4), 256>>>(Wq, Wk, Wv, Wo, w, W4);

    QkvArgs qa;
    qa.bias[0] = bq; qa.bias[1] = bk; qa.bias[2] = bv;
    qa.C[0] = qh; qa.C[1] = kh; qa.C[2] = vh;
    tc_gemm_qkv<<<dim3(DIM / 128, ROWS_TOT / 128, 3), 256, TC_SMEM_BYTES>>>(
        act, w, qa, ROWS_TOT, DIM, DIM);

    attn_fused<<<dim3(SS / QROWS, BB * NH), 128, FUS_SMEM>>>(
        qh, kh, vh, attn_ptr, rh);

    tc_gemm_out<<<dim3(DIM / 128, ROWS_TOT / 128), 256, TC_SMEM_BYTES>>>(
        rh, w + (size_t)3 * DIM * DIM, bo, out_ptr, ROWS_TOT, DIM, DIM);
}

// round 16
// speedup vs baseline: 1.0494x; 1.0494x over previous
#include <cuda_runtime.h>
#include <cuda_fp16.h>
#include <cstddef>
#include <cstdint>

// ---------------------------------------------------------------------------
// MultiHeadAttention: B=2, S=2048, DIM=1024, H=16, Dh=64, fp32.
// Outputs: out [2,2048,1024] then attn [2,16,2048,2048] (flattened tuple).
//
// R16: exactly R14's attention dataflow (normalized-P MMA, fp32 store path,
//      ex2.approx.f16x2) + Q projection pre-scaled by log2e/8, deleting the
//      per-element EXP_C FMUL from both sweeps' critical chains.
// ---------------------------------------------------------------------------

#define BB 2
#define SS 2048
#define DIM 1024
#define NH 16
#define DH 64
#define ROWS_TOT (BB*SS)          // 4096

// exp(s/8) = 2^(s * 0.125 * log2 e); folded into Q at projection time
#define EXP_C 0.18033688011112042f

__device__ __forceinline__ uint32_t smem_to_u32(const void* p) {
    uint32_t a;
    asm("{ .reg .u64 t; cvta.to.shared.u64 t, %1; cvt.u32.u64 %0, t; }" : "=r"(a) : "l"(p));
    return a;
}

#define CP_ASYNC16(dst_u32, src_ptr) \
    asm volatile("cp.async.cg.shared.global [%0], [%1], 16;" \
                 :: "r"(dst_u32), "l"(src_ptr))
#define CP_COMMIT() asm volatile("cp.async.commit_group;" ::: "memory")
#define CP_WAIT1()  asm volatile("cp.async.wait_group 1;" ::: "memory")
#define CP_WAIT0()  asm volatile("cp.async.wait_group 0;" ::: "memory")

__device__ __forceinline__ void ldsm4(uint32_t* r, uint32_t addr) {
    asm volatile("ldmatrix.sync.aligned.m8n8.x4.shared.b16 {%0,%1,%2,%3}, [%4];"
        : "=r"(r[0]), "=r"(r[1]), "=r"(r[2]), "=r"(r[3]) : "r"(addr));
}
__device__ __forceinline__ void ldsm4t(uint32_t* r, uint32_t addr) {
    asm volatile("ldmatrix.sync.aligned.m8n8.x4.trans.shared.b16 {%0,%1,%2,%3}, [%4];"
        : "=r"(r[0]), "=r"(r[1]), "=r"(r[2]), "=r"(r[3]) : "r"(addr));
}
__device__ __forceinline__ void mma16816(float* c, const uint32_t* a, const uint32_t* b) {
    asm volatile("mma.sync.aligned.m16n8k16.row.col.f32.f16.f16.f32 "
        "{%0,%1,%2,%3}, {%4,%5,%6,%7}, {%8,%9}, {%0,%1,%2,%3};"
        : "+f"(c[0]), "+f"(c[1]), "+f"(c[2]), "+f"(c[3])
        : "r"(a[0]), "r"(a[1]), "r"(a[2]), "r"(a[3]), "r"(b[0]), "r"(b[1]));
}
__device__ __forceinline__ uint32_t pack2h(float a, float b) {
    __half2 t = __floats2half2_rn(a, b);
    return *(uint32_t*)&t;
}
// two exp2 in one MUFU op
__device__ __forceinline__ uint32_t h2ex2(uint32_t x) {
    uint32_t r;
    asm("ex2.approx.f16x2 %0, %1;" : "=r"(r) : "r"(x));
    return r;
}
__device__ __forceinline__ float2 h2f2(uint32_t h) {
    return __half22float2(*(__half2*)&h);
}
__device__ __forceinline__ void stg_cs_v2(float* p, float x, float y) {
    asm volatile("st.global.cs.v2.f32 [%0], {%1, %2};" :: "l"(p), "f"(x), "f"(y) : "memory");
}

// ---------------- scratch (device globals) ----------------------------------
__device__ float g_dummy[ROWS_TOT * DIM];
__device__ __half g_act[3 * ROWS_TOT * DIM];
__device__ __half g_w[4 * DIM * DIM];
__device__ __half g_qh[ROWS_TOT * DIM];
__device__ __half g_kh[ROWS_TOT * DIM];
__device__ __half g_vh[ROWS_TOT * DIM];
__device__ __half g_rh[ROWS_TOT * DIM];

// ---------------------------------------------------------------------------
// batched fp32 -> fp16 converters
// ---------------------------------------------------------------------------
__global__ __launch_bounds__(256)
void cvt3(const float* __restrict__ s0, const float* __restrict__ s1,
          const float* __restrict__ s2, __half* __restrict__ dst, int n4)
{
    int i = blockIdx.x * blockDim.x + threadIdx.x;
    if (i >= n4) return;
    int z = blockIdx.z;
    const float* src = (z == 0) ? s0 : (z == 1) ? s1 : s2;
    __half* d = dst + (size_t)z * n4 * 4;
    float4 v = ((const float4*)src)[i];
    ((uint32_t*)d)[2 * i]     = pack2h(v.x, v.y);
    ((uint32_t*)d)[2 * i + 1] = pack2h(v.z, v.w);
}

__global__ __launch_bounds__(256)
void cvt4(const float* __restrict__ s0, const float* __restrict__ s1,
          const float* __restrict__ s2, const float* __restrict__ s3,
          __half* __restrict__ dst, int n4)
{
    int i = blockIdx.x * blockDim.x + threadIdx.x;
    if (i >= n4) return;
    int z = blockIdx.z;
    const float* src = (z == 0) ? s0 : (z == 1) ? s1 : (z == 2) ? s2 : s3;
    __half* d = dst + (size_t)z * n4 * 4;
    float4 v = ((const float4*)src)[i];
    ((uint32_t*)d)[2 * i]     = pack2h(v.x, v.y);
    ((uint32_t*)d)[2 * i + 1] = pack2h(v.z, v.w);
}

// ---------------------------------------------------------------------------
// fp16 HMMA GEMM core; epilogue scaled by cscale (used to pre-scale Q).
// ---------------------------------------------------------------------------
#define KC 64
#define PLANE 16384
#define TCBUF (2 * PLANE)
#define TC_SMEM_BYTES (2 * TCBUF)     // 65536

struct QkvArgs {
    const float* bias[3];
    __half* C[3];
};

__device__ __forceinline__ void gemm_body(
    const __half* __restrict__ A, const __half* __restrict__ W,
    const float* __restrict__ bias, float cscale, float* __restrict__ Cf,
    __half* __restrict__ Ch, int M, int N, int K, char* smem)
{
    uint32_t sb = smem_to_u32(smem);
    int tid = threadIdx.x;
    int warp = tid >> 5, lane = tid & 31;
    int n0 = blockIdx.x * 128;
    int m0 = blockIdx.y * 128;
    int wm = warp & 1, wn = warp >> 1;

    const __half* srcs[2] = { A + (size_t)m0 * K, W + (size_t)n0 * K };
    int lr = tid >> 3, lg = tid & 7;

    auto issue = [&](int c, int buf) {
        uint32_t bufb = sb + buf * TCBUF;
#pragma unroll
        for (int op = 0; op < 2; op++) {
            const __half* s = srcs[op] + c * KC;
            uint32_t pb = bufb + op * PLANE;
#pragma unroll
            for (int l = 0; l < 4; l++) {
                int r = lr + l * 32;
                uint32_t d = pb + r * 128 + ((lg ^ (r & 7)) << 4);
                CP_ASYNC16(d, s + (size_t)r * K + lg * 8);
            }
        }
        CP_COMMIT();
    };

    float acc[16][4];
#pragma unroll
    for (int i = 0; i < 16; i++)
#pragma unroll
        for (int j = 0; j < 4; j++) acc[i][j] = 0.f;

    int nch = K / KC;
    issue(0, 0);
    int r8 = lane & 7, grp = lane >> 3;

    for (int ch = 0; ch < nch; ch++) {
        int buf = ch & 1;
        if (ch + 1 < nch) { issue(ch + 1, buf ^ 1); CP_WAIT1(); }
        else              { CP_WAIT0(); }
        __syncthreads();

        uint32_t Ap = sb + buf * TCBUF;
        uint32_t Bp = Ap + PLANE;

#pragma unroll
        for (int ks = 0; ks < 4; ks++) {
            int c0 = ks * 2;
            uint32_t af[4][4], bf[8];
#pragma unroll
            for (int mf = 0; mf < 4; mf++) {
                int row = wm * 64 + mf * 16 + (grp & 1) * 8 + r8;
                int ck = c0 + (grp >> 1);
                uint32_t off = row * 128 + ((ck ^ (row & 7)) << 4);
                ldsm4(af[mf], Ap + off);
            }
#pragma unroll
            for (int p = 0; p < 2; p++) {
                int row = wn * 32 + p * 16 + (grp >> 1) * 8 + r8;
                int ck = c0 + (grp & 1);
                uint32_t off = row * 128 + ((ck ^ (row & 7)) << 4);
                ldsm4(&bf[p * 4], Bp + off);
            }
#pragma unroll
            for (int mf = 0; mf < 4; mf++)
#pragma unroll
                for (int nf = 0; nf < 4; nf++)
                    mma16816(acc[mf * 4 + nf], af[mf], &bf[nf * 2]);
        }
        __syncthreads();
    }

    int erow = lane >> 2, ecol = (lane & 3) * 2;
#pragma unroll
    for (int mf = 0; mf < 4; mf++) {
#pragma unroll
        for (int nf = 0; nf < 4; nf++) {
            float* cc = acc[mf * 4 + nf];
            int gm = m0 + wm * 64 + mf * 16 + erow;
            int gn = n0 + wn * 32 + nf * 8 + ecol;
            float2 b2 = *(const float2*)(bias + gn);
            float f0 = (cc[0] + b2.x) * cscale, f1 = (cc[1] + b2.y) * cscale;
            float f2 = (cc[2] + b2.x) * cscale, f3 = (cc[3] + b2.y) * cscale;
            if (Cf) {
                *(float2*)(Cf + (size_t)gm * N + gn)       = make_float2(f0, f1);
                *(float2*)(Cf + (size_t)(gm + 8) * N + gn) = make_float2(f2, f3);
            } else {
                *(uint32_t*)(Ch + (size_t)gm * N + gn)       = pack2h(f0, f1);
                *(uint32_t*)(Ch + (size_t)(gm + 8) * N + gn) = pack2h(f2, f3);
            }
        }
    }
}

__global__ __launch_bounds__(256)
void tc_gemm_qkv(const __half* __restrict__ act, const __half* __restrict__ w,
                 QkvArgs args, int M, int N, int K)
{
    extern __shared__ __align__(1024) char smem[];
    int z = blockIdx.z;
    float cs = (z == 0) ? EXP_C : 1.f;   // pre-scale Q for ex2
    gemm_body(act + (size_t)z * ROWS_TOT * DIM, w + (size_t)z * DIM * DIM,
              args.bias[z], cs, nullptr, args.C[z], M, N, K, smem);
}

__global__ __launch_bounds__(256)
void tc_gemm_out(const __half* __restrict__ A, const __half* __restrict__ W,
                 const float* __restrict__ bias, float* __restrict__ Cf,
                 int M, int N, int K)
{
    extern __shared__ __align__(1024) char smem[];
    gemm_body(A, W, bias, 1.f, Cf, nullptr, M, N, K, smem);
}

// ---------------------------------------------------------------------------
// attn_fused: CTA = (64 q-rows, bh), 128 threads = 4 warps = 2 qg x 2 nh.
// Warp (qg, nh): q rows [qg*32,+32) (2 mf), n/k cols [nh*64,+64). 2 CTAs/SM.
// Scores arrive pre-scaled (Q * log2e/8): ex2 directly on sc.
// sweep1: rowsum(ex2(sc)); n-pair sums combined via smem.
// sweep2: recompute sc, p = ex2(sc)*inv (fp32), st.cs attn write, pack fp16
//         -> AV mma (R14 dataflow), reps -> fp16.
// smem: Q plane 8KB (sums after kt0) + 2 stages x (K16 + V16) = 72KB.
// ---------------------------------------------------------------------------
#define QROWS 64
#define FUS_SMEM (8192 + 2 * 32768)   // 73728

__global__ __launch_bounds__(128, 2)
void attn_fused(const __half* __restrict__ qh, const __half* __restrict__ kh,
                const __half* __restrict__ vh,
                float* __restrict__ attn, __half* __restrict__ reps)
{
    extern __shared__ __align__(1024) char smem[];
    uint32_t sb = smem_to_u32(smem);

    int tid = threadIdx.x;
    int warp = tid >> 5, lane = tid & 31;
    int r8 = lane & 7, grp = lane >> 3;
    int qg = warp >> 1, nh = warp & 1;
    int bh = blockIdx.y;
    int b = bh >> 4, h = bh & 15;
    int s0 = blockIdx.x * QROWS;

    const __half* qB = qh + ((size_t)(b * SS + s0)) * DIM + h * DH;
    const __half* kB = kh + ((size_t)b * SS) * DIM + h * DH;
    const __half* vB = vh + ((size_t)b * SS) * DIM + h * DH;

    int lr = tid >> 3, lg = tid & 7;   // lr 0..15

    auto load_plane128 = [&](uint32_t dst, const __half* src) {
#pragma unroll
        for (int l = 0; l < 8; l++) {
            int r = lr + l * 16;
            uint32_t d = dst + r * 128 + ((lg ^ (r & 7)) << 4);
            CP_ASYNC16(d, src + (size_t)r * DIM + lg * 8);
        }
    };
    auto load_plane64 = [&](uint32_t dst, const __half* src) {
#pragma unroll
        for (int l = 0; l < 4; l++) {
            int r = lr + l * 16;
            uint32_t d = dst + r * 128 + ((lg ^ (r & 7)) << 4);
            CP_ASYNC16(d, src + (size_t)r * DIM + lg * 8);
        }
    };
    auto issue_k = [&](int kt, int slot) {
        uint32_t stg = sb + 8192 + slot * 32768;
        load_plane128(stg, kB + (size_t)(kt * 128) * DIM);
        CP_COMMIT();
    };
    auto issue_kv = [&](int kt, int slot) {
        uint32_t stg = sb + 8192 + slot * 32768;
        load_plane128(stg, kB + (size_t)(kt * 128) * DIM);
        load_plane128(stg + 16384, vB + (size_t)(kt * 128) * DIM);
        CP_COMMIT();
    };

    load_plane64(sb, qB);              // Q plane: 64 rows
    issue_k(0, 0);
    issue_k(1, 1);

    uint32_t qf[2][4][4];              // [mf][ks]
    float sA[2] = {0.f, 0.f}, sB[2] = {0.f, 0.f};

    // score compute for one K tile: warp's 32q x 64n (scores pre-scaled)
    auto compute_scores = [&](uint32_t Kp, float sc[2][8][4]) {
#pragma unroll
        for (int mf = 0; mf < 2; mf++)
#pragma unroll
            for (int nt = 0; nt < 8; nt++)
#pragma unroll
                for (int j = 0; j < 4; j++) sc[mf][nt][j] = 0.f;
#pragma unroll
        for (int ks = 0; ks < 4; ks++) {
#pragma unroll
            for (int p = 0; p < 4; p++) {
                uint32_t bf[4];
                int gp = nh * 4 + p;
                int row = gp * 16 + (grp >> 1) * 8 + r8;
                int ck = ks * 2 + (grp & 1);
                uint32_t off = row * 128 + ((ck ^ (row & 7)) << 4);
                ldsm4(bf, Kp + off);
#pragma unroll
                for (int mf = 0; mf < 2; mf++)
#pragma unroll
                    for (int t = 0; t < 2; t++)
                        mma16816(sc[mf][2 * p + t], qf[mf][ks], &bf[t * 2]);
            }
        }
    };

    // -------- sweep 1: row sums --------
    for (int kt = 0; kt < 16; kt++) {
        if (kt == 15) { CP_WAIT0(); } else { CP_WAIT1(); }
        __syncthreads();

        if (kt == 0) {
#pragma unroll
            for (int mf = 0; mf < 2; mf++)
#pragma unroll
                for (int ks = 0; ks < 4; ks++) {
                    int row = qg * 32 + mf * 16 + (grp & 1) * 8 + r8;
                    int ck = ks * 2 + (grp >> 1);
                    uint32_t off = row * 128 + ((ck ^ (row & 7)) << 4);
                    ldsm4(qf[mf][ks], sb + off);
                }
        }

        uint32_t Kp = sb + 8192 + (kt & 1) * 32768;
        float sc[2][8][4];
        compute_scores(Kp, sc);

#pragma unroll
        for (int mf = 0; mf < 2; mf++)
#pragma unroll
            for (int nt = 0; nt < 8; nt++) {
                uint32_t pu0 = h2ex2(pack2h(sc[mf][nt][0], sc[mf][nt][1]));
                uint32_t pu1 = h2ex2(pack2h(sc[mf][nt][2], sc[mf][nt][3]));
                float2 fA = h2f2(pu0), fB = h2f2(pu1);
                sA[mf] += fA.x + fA.y;
                sB[mf] += fB.x + fB.y;
            }
        __syncthreads();
        if (kt + 2 < 16) issue_k(kt + 2, kt & 1);
    }

    // combine n-pair partial sums via smem (Q plane, dead after kt0)
    float* sums = (float*)smem;   // [64][2]
#pragma unroll
    for (int mf = 0; mf < 2; mf++) {
        sA[mf] += __shfl_xor_sync(~0u, sA[mf], 1);
        sA[mf] += __shfl_xor_sync(~0u, sA[mf], 2);
        sB[mf] += __shfl_xor_sync(~0u, sB[mf], 1);
        sB[mf] += __shfl_xor_sync(~0u, sB[mf], 2);
    }
    if ((lane & 3) == 0) {
#pragma unroll
        for (int mf = 0; mf < 2; mf++) {
            int r = qg * 32 + mf * 16 + (lane >> 2);
            sums[r * 2 + nh]       = sA[mf];
            sums[(r + 8) * 2 + nh] = sB[mf];
        }
    }
    issue_kv(0, 0);
    issue_kv(1, 1);
    __syncthreads();

    float invA[2], invB[2];
#pragma unroll
    for (int mf = 0; mf < 2; mf++) {
        int r = qg * 32 + mf * 16 + (lane >> 2);
        invA[mf] = 1.f / (sums[r * 2] + sums[r * 2 + 1]);
        invB[mf] = 1.f / (sums[(r + 8) * 2] + sums[(r + 8) * 2 + 1]);
    }

    // -------- sweep 2: attn write + AV (warp's k-half, R14 dataflow) --------
    float avacc[2][8][4];
#pragma unroll
    for (int mf = 0; mf < 2; mf++)
#pragma unroll
        for (int i = 0; i < 8; i++)
#pragma unroll
            for (int j = 0; j < 4; j++) avacc[mf][i][j] = 0.f;

    for (int kt = 0; kt < 16; kt++) {
        if (kt == 15) { CP_WAIT0(); } else { CP_WAIT1(); }
        __syncthreads();

        uint32_t stg = sb + 8192 + (kt & 1) * 32768;
        uint32_t Kp = stg, Vp = stg + 16384;

        float sc[2][8][4];
        compute_scores(Kp, sc);

        float* a0 = attn + ((size_t)bh * SS + (s0 + qg * 32 + (lane >> 2))) * SS
                  + kt * 128 + nh * 64 + (lane & 3) * 2;
#pragma unroll
        for (int j = 0; j < 4; j++) {          // AV k16 steps in warp's 64-slice
            uint32_t Pf[2][4];
#pragma unroll
            for (int mf = 0; mf < 2; mf++) {
                float* aA = a0 + (size_t)(mf * 16) * SS;
                float* aB = aA + (size_t)8 * SS;
#pragma unroll
                for (int t = 0; t < 2; t++) {
                    int nt = 2 * j + t;
                    uint32_t pu0 = h2ex2(pack2h(sc[mf][nt][0], sc[mf][nt][1]));
                    uint32_t pu1 = h2ex2(pack2h(sc[mf][nt][2], sc[mf][nt][3]));
                    float2 fA = h2f2(pu0), fB = h2f2(pu1);
                    float p0 = fA.x * invA[mf], p1 = fA.y * invA[mf];
                    float p2 = fB.x * invB[mf], p3 = fB.y * invB[mf];
                    stg_cs_v2(aA + nt * 8, p0, p1);
                    stg_cs_v2(aB + nt * 8, p2, p3);
                    Pf[mf][t * 2]     = pack2h(p0, p1);
                    Pf[mf][t * 2 + 1] = pack2h(p2, p3);
                }
            }
#pragma unroll
            for (int p = 0; p < 4; p++) {      // d16 pairs
                uint32_t vf[4];
                int srow = nh * 64 + j * 16 + (lane & 15);
                int ck = p * 2 + (lane >> 4);
                uint32_t off = srow * 128 + ((ck ^ (srow & 7)) << 4);
                ldsm4t(vf, Vp + off);
#pragma unroll
                for (int mf = 0; mf < 2; mf++)
#pragma unroll
                    for (int t = 0; t < 2; t++)
                        mma16816(avacc[mf][2 * p + t], Pf[mf], &vf[t * 2]);
            }
        }
        __syncthreads();
        if (kt + 2 < 16) issue_kv(kt + 2, kt & 1);
    }

    // -------- combine AV n-pair partials, write reps --------
    __syncthreads();
    float* buf = (float*)(smem + 8192);   // [64][72] in dead staging area
    if (nh == 1) {
#pragma unroll
        for (int mf = 0; mf < 2; mf++)
#pragma unroll
            for (int nt = 0; nt < 8; nt++) {
                int r = qg * 32 + mf * 16 + (lane >> 2);
                int c = nt * 8 + (lane & 3) * 2;
                *(float2*)&buf[r * 72 + c] =
                    make_float2(avacc[mf][nt][0], avacc[mf][nt][1]);
                *(float2*)&buf[(r + 8) * 72 + c] =
                    make_float2(avacc[mf][nt][2], avacc[mf][nt][3]);
            }
    }
    __syncthreads();
    if (nh == 0) {
        int rowbase = b * SS + s0;
#pragma unroll
        for (int mf = 0; mf < 2; mf++)
#pragma unroll
            for (int nt = 0; nt < 8; nt++) {
                int r = qg * 32 + mf * 16 + (lane >> 2);
                int c = nt * 8 + (lane & 3) * 2;
                float2 o0 = *(float2*)&buf[r * 72 + c];
                float2 o1 = *(float2*)&buf[(r + 8) * 72 + c];
                int gn = h * DH + c;
                *(uint32_t*)(reps + (size_t)(rowbase + r) * DIM + gn) =
                    pack2h(avacc[mf][nt][0] + o0.x, avacc[mf][nt][1] + o0.y);
                *(uint32_t*)(reps + (size_t)(rowbase + r + 8) * DIM + gn) =
                    pack2h(avacc[mf][nt][2] + o1.x, avacc[mf][nt][3] + o1.y);
            }
    }
}

// ---------------------------------------------------------------------------
extern "C" void kernel_launch(void* const* d_in, const int* in_sizes, int n_in,
                              void* d_out, int out_size)
{
    const float* xq = (const float*)d_in[0];
    const float* xk = (const float*)d_in[1];
    const float* xv = (const float*)d_in[2];
    const float* Wq = (const float*)d_in[3];
    const float* bq = (const float*)d_in[4];
    const float* Wk = (const float*)d_in[5];
    const float* bk = (const float*)d_in[6];
    const float* Wv = (const float*)d_in[7];
    const float* bv = (const float*)d_in[8];
    const float* Wo = (const float*)d_in[9];
    const float* bo = (const float*)d_in[10];

    float* pd;
    __half *act, *w, *qh, *kh, *vh, *rh;
    cudaGetSymbolAddress((void**)&pd, g_dummy);
    cudaGetSymbolAddress((void**)&act, g_act);
    cudaGetSymbolAddress((void**)&w, g_w);
    cudaGetSymbolAddress((void**)&qh, g_qh);
    cudaGetSymbolAddress((void**)&kh, g_kh);
    cudaGetSymbolAddress((void**)&vh, g_vh);
    cudaGetSymbolAddress((void**)&rh, g_rh);

    const size_t OUT_ELEMS = (size_t)ROWS_TOT * DIM;
    const size_t ATT_ELEMS = (size_t)BB * NH * SS * SS;

    float* out_ptr = (float*)d_out;
    float* attn_ptr = (float*)d_out + OUT_ELEMS;
    size_t osz = (size_t)out_size;
    if (osz == ATT_ELEMS) {
        attn_ptr = (float*)d_out;
        out_ptr = pd;
    }

    cudaFuncSetAttribute(tc_gemm_qkv, cudaFuncAttributeMaxDynamicSharedMemorySize,
                         TC_SMEM_BYTES);
    cudaFuncSetAttribute(tc_gemm_out, cudaFuncAttributeMaxDynamicSharedMemorySize,
                         TC_SMEM_BYTES);
    cudaFuncSetAttribute(attn_fused, cudaFuncAttributeMaxDynamicSharedMemorySize,
                         FUS_SMEM);

    const int ACT4 = ROWS_TOT * DIM / 4;
    const int W4   = DIM * DIM / 4;

    cvt3<<<dim3((ACT4 + 255) / 256, 1, 3), 256>>>(xq, xk, xv, act, ACT4);
    cvt4<<<dim3((W4 + 255) / 256, 1, 4), 256>>>(Wq, Wk, Wv, Wo, w, W4);

    QkvArgs qa;
    qa.bias[0] = bq; qa.bias[1] = bk; qa.bias[2] = bv;
    qa.C[0] = qh; qa.C[1] = kh; qa.C[2] = vh;
    tc_gemm_qkv<<<dim3(DIM / 128, ROWS_TOT / 128, 3), 256, TC_SMEM_BYTES>>>(
        act, w, qa, ROWS_TOT, DIM, DIM);

    attn_fused<<<dim3(SS / QROWS, BB * NH), 128, FUS_SMEM>>>(
        qh, kh, vh, attn_ptr, rh);

    tc_gemm_out<<<dim3(DIM / 128, ROWS_TOT / 128), 256, TC_SMEM_BYTES>>>(
        rh, w + (size_t)3 * DIM * DIM, bo, out_ptr, ROWS_TOT, DIM, DIM);
}

// round 17
// speedup vs baseline: 1.0717x; 1.0213x over previous
#include <cuda_runtime.h>
#include <cuda_fp16.h>
#include <cstddef>
#include <cstdint>

// ---------------------------------------------------------------------------
// MultiHeadAttention: B=2, S=2048, DIM=1024, H=16, Dh=64, fp32.
// Outputs: out [2,2048,1024] then attn [2,16,2048,2048] (flattened tuple).
//
// R17: R16 + register-diet attn for 3 CTAs/SM. Score MMA fused with its
//      consumer per j-block (sc live range 64 -> 16 regs) in both sweeps;
//      __launch_bounds__(128,3). Everything else identical to R16.
// ---------------------------------------------------------------------------

#define BB 2
#define SS 2048
#define DIM 1024
#define NH 16
#define DH 64
#define ROWS_TOT (BB*SS)          // 4096

// exp(s/8) = 2^(s * 0.125 * log2 e); folded into Q at projection time
#define EXP_C 0.18033688011112042f

__device__ __forceinline__ uint32_t smem_to_u32(const void* p) {
    uint32_t a;
    asm("{ .reg .u64 t; cvta.to.shared.u64 t, %1; cvt.u32.u64 %0, t; }" : "=r"(a) : "l"(p));
    return a;
}

#define CP_ASYNC16(dst_u32, src_ptr) \
    asm volatile("cp.async.cg.shared.global [%0], [%1], 16;" \
                 :: "r"(dst_u32), "l"(src_ptr))
#define CP_COMMIT() asm volatile("cp.async.commit_group;" ::: "memory")
#define CP_WAIT1()  asm volatile("cp.async.wait_group 1;" ::: "memory")
#define CP_WAIT0()  asm volatile("cp.async.wait_group 0;" ::: "memory")

__device__ __forceinline__ void ldsm4(uint32_t* r, uint32_t addr) {
    asm volatile("ldmatrix.sync.aligned.m8n8.x4.shared.b16 {%0,%1,%2,%3}, [%4];"
        : "=r"(r[0]), "=r"(r[1]), "=r"(r[2]), "=r"(r[3]) : "r"(addr));
}
__device__ __forceinline__ void ldsm4t(uint32_t* r, uint32_t addr) {
    asm volatile("ldmatrix.sync.aligned.m8n8.x4.trans.shared.b16 {%0,%1,%2,%3}, [%4];"
        : "=r"(r[0]), "=r"(r[1]), "=r"(r[2]), "=r"(r[3]) : "r"(addr));
}
__device__ __forceinline__ void mma16816(float* c, const uint32_t* a, const uint32_t* b) {
    asm volatile("mma.sync.aligned.m16n8k16.row.col.f32.f16.f16.f32 "
        "{%0,%1,%2,%3}, {%4,%5,%6,%7}, {%8,%9}, {%0,%1,%2,%3};"
        : "+f"(c[0]), "+f"(c[1]), "+f"(c[2]), "+f"(c[3])
        : "r"(a[0]), "r"(a[1]), "r"(a[2]), "r"(a[3]), "r"(b[0]), "r"(b[1]));
}
__device__ __forceinline__ uint32_t pack2h(float a, float b) {
    __half2 t = __floats2half2_rn(a, b);
    return *(uint32_t*)&t;
}
// two exp2 in one MUFU op
__device__ __forceinline__ uint32_t h2ex2(uint32_t x) {
    uint32_t r;
    asm("ex2.approx.f16x2 %0, %1;" : "=r"(r) : "r"(x));
    return r;
}
__device__ __forceinline__ float2 h2f2(uint32_t h) {
    return __half22float2(*(__half2*)&h);
}
__device__ __forceinline__ void stg_cs_v2(float* p, float x, float y) {
    asm volatile("st.global.cs.v2.f32 [%0], {%1, %2};" :: "l"(p), "f"(x), "f"(y) : "memory");
}

// ---------------- scratch (device globals) ----------------------------------
__device__ float g_dummy[ROWS_TOT * DIM];
__device__ __half g_act[3 * ROWS_TOT * DIM];
__device__ __half g_w[4 * DIM * DIM];
__device__ __half g_qh[ROWS_TOT * DIM];
__device__ __half g_kh[ROWS_TOT * DIM];
__device__ __half g_vh[ROWS_TOT * DIM];
__device__ __half g_rh[ROWS_TOT * DIM];

// ---------------------------------------------------------------------------
// batched fp32 -> fp16 converters
// ---------------------------------------------------------------------------
__global__ __launch_bounds__(256)
void cvt3(const float* __restrict__ s0, const float* __restrict__ s1,
          const float* __restrict__ s2, __half* __restrict__ dst, int n4)
{
    int i = blockIdx.x * blockDim.x + threadIdx.x;
    if (i >= n4) return;
    int z = blockIdx.z;
    const float* src = (z == 0) ? s0 : (z == 1) ? s1 : s2;
    __half* d = dst + (size_t)z * n4 * 4;
    float4 v = ((const float4*)src)[i];
    ((uint32_t*)d)[2 * i]     = pack2h(v.x, v.y);
    ((uint32_t*)d)[2 * i + 1] = pack2h(v.z, v.w);
}

__global__ __launch_bounds__(256)
void cvt4(const float* __restrict__ s0, const float* __restrict__ s1,
          const float* __restrict__ s2, const float* __restrict__ s3,
          __half* __restrict__ dst, int n4)
{
    int i = blockIdx.x * blockDim.x + threadIdx.x;
    if (i >= n4) return;
    int z = blockIdx.z;
    const float* src = (z == 0) ? s0 : (z == 1) ? s1 : (z == 2) ? s2 : s3;
    __half* d = dst + (size_t)z * n4 * 4;
    float4 v = ((const float4*)src)[i];
    ((uint32_t*)d)[2 * i]     = pack2h(v.x, v.y);
    ((uint32_t*)d)[2 * i + 1] = pack2h(v.z, v.w);
}

// ---------------------------------------------------------------------------
// fp16 HMMA GEMM core; epilogue scaled by cscale (used to pre-scale Q).
// ---------------------------------------------------------------------------
#define KC 64
#define PLANE 16384
#define TCBUF (2 * PLANE)
#define TC_SMEM_BYTES (2 * TCBUF)     // 65536

struct QkvArgs {
    const float* bias[3];
    __half* C[3];
};

__device__ __forceinline__ void gemm_body(
    const __half* __restrict__ A, const __half* __restrict__ W,
    const float* __restrict__ bias, float cscale, float* __restrict__ Cf,
    __half* __restrict__ Ch, int M, int N, int K, char* smem)
{
    uint32_t sb = smem_to_u32(smem);
    int tid = threadIdx.x;
    int warp = tid >> 5, lane = tid & 31;
    int n0 = blockIdx.x * 128;
    int m0 = blockIdx.y * 128;
    int wm = warp & 1, wn = warp >> 1;

    const __half* srcs[2] = { A + (size_t)m0 * K, W + (size_t)n0 * K };
    int lr = tid >> 3, lg = tid & 7;

    auto issue = [&](int c, int buf) {
        uint32_t bufb = sb + buf * TCBUF;
#pragma unroll
        for (int op = 0; op < 2; op++) {
            const __half* s = srcs[op] + c * KC;
            uint32_t pb = bufb + op * PLANE;
#pragma unroll
            for (int l = 0; l < 4; l++) {
                int r = lr + l * 32;
                uint32_t d = pb + r * 128 + ((lg ^ (r & 7)) << 4);
                CP_ASYNC16(d, s + (size_t)r * K + lg * 8);
            }
        }
        CP_COMMIT();
    };

    float acc[16][4];
#pragma unroll
    for (int i = 0; i < 16; i++)
#pragma unroll
        for (int j = 0; j < 4; j++) acc[i][j] = 0.f;

    int nch = K / KC;
    issue(0, 0);
    int r8 = lane & 7, grp = lane >> 3;

    for (int ch = 0; ch < nch; ch++) {
        int buf = ch & 1;
        if (ch + 1 < nch) { issue(ch + 1, buf ^ 1); CP_WAIT1(); }
        else              { CP_WAIT0(); }
        __syncthreads();

        uint32_t Ap = sb + buf * TCBUF;
        uint32_t Bp = Ap + PLANE;

#pragma unroll
        for (int ks = 0; ks < 4; ks++) {
            int c0 = ks * 2;
            uint32_t af[4][4], bf[8];
#pragma unroll
            for (int mf = 0; mf < 4; mf++) {
                int row = wm * 64 + mf * 16 + (grp & 1) * 8 + r8;
                int ck = c0 + (grp >> 1);
                uint32_t off = row * 128 + ((ck ^ (row & 7)) << 4);
                ldsm4(af[mf], Ap + off);
            }
#pragma unroll
            for (int p = 0; p < 2; p++) {
                int row = wn * 32 + p * 16 + (grp >> 1) * 8 + r8;
                int ck = c0 + (grp & 1);
                uint32_t off = row * 128 + ((ck ^ (row & 7)) << 4);
                ldsm4(&bf[p * 4], Bp + off);
            }
#pragma unroll
            for (int mf = 0; mf < 4; mf++)
#pragma unroll
                for (int nf = 0; nf < 4; nf++)
                    mma16816(acc[mf * 4 + nf], af[mf], &bf[nf * 2]);
        }
        __syncthreads();
    }

    int erow = lane >> 2, ecol = (lane & 3) * 2;
#pragma unroll
    for (int mf = 0; mf < 4; mf++) {
#pragma unroll
        for (int nf = 0; nf < 4; nf++) {
            float* cc = acc[mf * 4 + nf];
            int gm = m0 + wm * 64 + mf * 16 + erow;
            int gn = n0 + wn * 32 + nf * 8 + ecol;
            float2 b2 = *(const float2*)(bias + gn);
            float f0 = (cc[0] + b2.x) * cscale, f1 = (cc[1] + b2.y) * cscale;
            float f2 = (cc[2] + b2.x) * cscale, f3 = (cc[3] + b2.y) * cscale;
            if (Cf) {
                *(float2*)(Cf + (size_t)gm * N + gn)       = make_float2(f0, f1);
                *(float2*)(Cf + (size_t)(gm + 8) * N + gn) = make_float2(f2, f3);
            } else {
                *(uint32_t*)(Ch + (size_t)gm * N + gn)       = pack2h(f0, f1);
                *(uint32_t*)(Ch + (size_t)(gm + 8) * N + gn) = pack2h(f2, f3);
            }
        }
    }
}

__global__ __launch_bounds__(256)
void tc_gemm_qkv(const __half* __restrict__ act, const __half* __restrict__ w,
                 QkvArgs args, int M, int N, int K)
{
    extern __shared__ __align__(1024) char smem[];
    int z = blockIdx.z;
    float cs = (z == 0) ? EXP_C : 1.f;   // pre-scale Q for ex2
    gemm_body(act + (size_t)z * ROWS_TOT * DIM, w + (size_t)z * DIM * DIM,
              args.bias[z], cs, nullptr, args.C[z], M, N, K, smem);
}

__global__ __launch_bounds__(256)
void tc_gemm_out(const __half* __restrict__ A, const __half* __restrict__ W,
                 const float* __restrict__ bias, float* __restrict__ Cf,
                 int M, int N, int K)
{
    extern __shared__ __align__(1024) char smem[];
    gemm_body(A, W, bias, 1.f, Cf, nullptr, M, N, K, smem);
}

// ---------------------------------------------------------------------------
// attn_fused: CTA = (64 q-rows, bh), 128 threads = 4 warps = 2 qg x 2 nh.
// Warp (qg, nh): q rows [qg*32,+32) (2 mf), n/k cols [nh*64,+64).
// Register-diet: score MMA fused with consumer per j-block (sc = 16 regs),
// __launch_bounds__(128,3) -> 3 CTAs/SM (smem 3x72KB = 216KB).
// sweep1: per j: score mma -> ex2 -> sums. n-pair sums combined via smem.
// sweep2: per j: score mma -> ex2 -> p=pu*inv -> st.cs attn + pack fp16 ->
//         AV mma. AV n-pair partials combined in smem; reps -> fp16.
// ---------------------------------------------------------------------------
#define QROWS 64
#define FUS_SMEM (8192 + 2 * 32768)   // 73728

__global__ __launch_bounds__(128, 3)
void attn_fused(const __half* __restrict__ qh, const __half* __restrict__ kh,
                const __half* __restrict__ vh,
                float* __restrict__ attn, __half* __restrict__ reps)
{
    extern __shared__ __align__(1024) char smem[];
    uint32_t sb = smem_to_u32(smem);

    int tid = threadIdx.x;
    int warp = tid >> 5, lane = tid & 31;
    int r8 = lane & 7, grp = lane >> 3;
    int qg = warp >> 1, nh = warp & 1;
    int bh = blockIdx.y;
    int b = bh >> 4, h = bh & 15;
    int s0 = blockIdx.x * QROWS;

    const __half* qB = qh + ((size_t)(b * SS + s0)) * DIM + h * DH;
    const __half* kB = kh + ((size_t)b * SS) * DIM + h * DH;
    const __half* vB = vh + ((size_t)b * SS) * DIM + h * DH;

    int lr = tid >> 3, lg = tid & 7;   // lr 0..15

    auto load_plane128 = [&](uint32_t dst, const __half* src) {
#pragma unroll
        for (int l = 0; l < 8; l++) {
            int r = lr + l * 16;
            uint32_t d = dst + r * 128 + ((lg ^ (r & 7)) << 4);
            CP_ASYNC16(d, src + (size_t)r * DIM + lg * 8);
        }
    };
    auto load_plane64 = [&](uint32_t dst, const __half* src) {
#pragma unroll
        for (int l = 0; l < 4; l++) {
            int r = lr + l * 16;
            uint32_t d = dst + r * 128 + ((lg ^ (r & 7)) << 4);
            CP_ASYNC16(d, src + (size_t)r * DIM + lg * 8);
        }
    };
    auto issue_k = [&](int kt, int slot) {
        uint32_t stg = sb + 8192 + slot * 32768;
        load_plane128(stg, kB + (size_t)(kt * 128) * DIM);
        CP_COMMIT();
    };
    auto issue_kv = [&](int kt, int slot) {
        uint32_t stg = sb + 8192 + slot * 32768;
        load_plane128(stg, kB + (size_t)(kt * 128) * DIM);
        load_plane128(stg + 16384, vB + (size_t)(kt * 128) * DIM);
        CP_COMMIT();
    };

    load_plane64(sb, qB);              // Q plane: 64 rows
    issue_k(0, 0);
    issue_k(1, 1);

    uint32_t qf[2][4][4];              // [mf][ks]
    float sA[2] = {0.f, 0.f}, sB[2] = {0.f, 0.f};

    // score mma for one j-block (16q x 16n per mf): sc[mf][t][4]
    auto score_block = [&](uint32_t Kp, int j, float sc[2][2][4]) {
#pragma unroll
        for (int mf = 0; mf < 2; mf++)
#pragma unroll
            for (int t = 0; t < 2; t++)
#pragma unroll
                for (int x = 0; x < 4; x++) sc[mf][t][x] = 0.f;
        int gp = nh * 4 + j;
        int row = gp * 16 + (grp >> 1) * 8 + r8;
#pragma unroll
        for (int ks = 0; ks < 4; ks++) {
            uint32_t bf[4];
            int ck = ks * 2 + (grp & 1);
            uint32_t off = row * 128 + ((ck ^ (row & 7)) << 4);
            ldsm4(bf, Kp + off);
#pragma unroll
            for (int mf = 0; mf < 2; mf++)
#pragma unroll
                for (int t = 0; t < 2; t++)
                    mma16816(sc[mf][t], qf[mf][ks], &bf[t * 2]);
        }
    };

    // -------- sweep 1: row sums --------
    for (int kt = 0; kt < 16; kt++) {
        if (kt == 15) { CP_WAIT0(); } else { CP_WAIT1(); }
        __syncthreads();

        if (kt == 0) {
#pragma unroll
            for (int mf = 0; mf < 2; mf++)
#pragma unroll
                for (int ks = 0; ks < 4; ks++) {
                    int row = qg * 32 + mf * 16 + (grp & 1) * 8 + r8;
                    int ck = ks * 2 + (grp >> 1);
                    uint32_t off = row * 128 + ((ck ^ (row & 7)) << 4);
                    ldsm4(qf[mf][ks], sb + off);
                }
        }

        uint32_t Kp = sb + 8192 + (kt & 1) * 32768;
#pragma unroll
        for (int j = 0; j < 4; j++) {
            float sc[2][2][4];
            score_block(Kp, j, sc);
#pragma unroll
            for (int mf = 0; mf < 2; mf++)
#pragma unroll
                for (int t = 0; t < 2; t++) {
                    uint32_t pu0 = h2ex2(pack2h(sc[mf][t][0], sc[mf][t][1]));
                    uint32_t pu1 = h2ex2(pack2h(sc[mf][t][2], sc[mf][t][3]));
                    float2 fA = h2f2(pu0), fB = h2f2(pu1);
                    sA[mf] += fA.x + fA.y;
                    sB[mf] += fB.x + fB.y;
                }
        }
        __syncthreads();
        if (kt + 2 < 16) issue_k(kt + 2, kt & 1);
    }

    // combine n-pair partial sums via smem (Q plane, dead after kt0)
    float* sums = (float*)smem;   // [64][2]
#pragma unroll
    for (int mf = 0; mf < 2; mf++) {
        sA[mf] += __shfl_xor_sync(~0u, sA[mf], 1);
        sA[mf] += __shfl_xor_sync(~0u, sA[mf], 2);
        sB[mf] += __shfl_xor_sync(~0u, sB[mf], 1);
        sB[mf] += __shfl_xor_sync(~0u, sB[mf], 2);
    }
    if ((lane & 3) == 0) {
#pragma unroll
        for (int mf = 0; mf < 2; mf++) {
            int r = qg * 32 + mf * 16 + (lane >> 2);
            sums[r * 2 + nh]       = sA[mf];
            sums[(r + 8) * 2 + nh] = sB[mf];
        }
    }
    issue_kv(0, 0);
    issue_kv(1, 1);
    __syncthreads();

    float invA[2], invB[2];
#pragma unroll
    for (int mf = 0; mf < 2; mf++) {
        int r = qg * 32 + mf * 16 + (lane >> 2);
        invA[mf] = 1.f / (sums[r * 2] + sums[r * 2 + 1]);
        invB[mf] = 1.f / (sums[(r + 8) * 2] + sums[(r + 8) * 2 + 1]);
    }

    // -------- sweep 2: attn write + AV (warp's k-half, fused per j) --------
    float avacc[2][8][4];
#pragma unroll
    for (int mf = 0; mf < 2; mf++)
#pragma unroll
        for (int i = 0; i < 8; i++)
#pragma unroll
            for (int j = 0; j < 4; j++) avacc[mf][i][j] = 0.f;

    for (int kt = 0; kt < 16; kt++) {
        if (kt == 15) { CP_WAIT0(); } else { CP_WAIT1(); }
        __syncthreads();

        uint32_t stg = sb + 8192 + (kt & 1) * 32768;
        uint32_t Kp = stg, Vp = stg + 16384;

        float* a0 = attn + ((size_t)bh * SS + (s0 + qg * 32 + (lane >> 2))) * SS
                  + kt * 128 + nh * 64 + (lane & 3) * 2;
#pragma unroll
        for (int j = 0; j < 4; j++) {          // fused score + AV k16 step
            float sc[2][2][4];
            score_block(Kp, j, sc);
            uint32_t Pf[2][4];
#pragma unroll
            for (int mf = 0; mf < 2; mf++) {
                float* aA = a0 + (size_t)(mf * 16) * SS;
                float* aB = aA + (size_t)8 * SS;
#pragma unroll
                for (int t = 0; t < 2; t++) {
                    int nt = 2 * j + t;
                    uint32_t pu0 = h2ex2(pack2h(sc[mf][t][0], sc[mf][t][1]));
                    uint32_t pu1 = h2ex2(pack2h(sc[mf][t][2], sc[mf][t][3]));
                    float2 fA = h2f2(pu0), fB = h2f2(pu1);
                    float p0 = fA.x * invA[mf], p1 = fA.y * invA[mf];
                    float p2 = fB.x * invB[mf], p3 = fB.y * invB[mf];
                    stg_cs_v2(aA + nt * 8, p0, p1);
                    stg_cs_v2(aB + nt * 8, p2, p3);
                    Pf[mf][t * 2]     = pack2h(p0, p1);
                    Pf[mf][t * 2 + 1] = pack2h(p2, p3);
                }
            }
#pragma unroll
            for (int pd = 0; pd < 4; pd++) {   // d16 pairs
                uint32_t vf[4];
                int srow = nh * 64 + j * 16 + (lane & 15);
                int ck = pd * 2 + (lane >> 4);
                uint32_t off = srow * 128 + ((ck ^ (srow & 7)) << 4);
                ldsm4t(vf, Vp + off);
#pragma unroll
                for (int mf = 0; mf < 2; mf++)
#pragma unroll
                    for (int t = 0; t < 2; t++)
                        mma16816(avacc[mf][2 * pd + t], Pf[mf], &vf[t * 2]);
            }
        }
        __syncthreads();
        if (kt + 2 < 16) issue_kv(kt + 2, kt & 1);
    }

    // -------- combine AV n-pair partials, write reps --------
    __syncthreads();
    float* buf = (float*)(smem + 8192);   // [64][72] in dead staging area
    if (nh == 1) {
#pragma unroll
        for (int mf = 0; mf < 2; mf++)
#pragma unroll
            for (int nt = 0; nt < 8; nt++) {
                int r = qg * 32 + mf * 16 + (lane >> 2);
                int c = nt * 8 + (lane & 3) * 2;
                *(float2*)&buf[r * 72 + c] =
                    make_float2(avacc[mf][nt][0], avacc[mf][nt][1]);
                *(float2*)&buf[(r + 8) * 72 + c] =
                    make_float2(avacc[mf][nt][2], avacc[mf][nt][3]);
            }
    }
    __syncthreads();
    if (nh == 0) {
        int rowbase = b * SS + s0;
#pragma unroll
        for (int mf = 0; mf < 2; mf++)
#pragma unroll
            for (int nt = 0; nt < 8; nt++) {
                int r = qg * 32 + mf * 16 + (lane >> 2);
                int c = nt * 8 + (lane & 3) * 2;
                float2 o0 = *(float2*)&buf[r * 72 + c];
                float2 o1 = *(float2*)&buf[(r + 8) * 72 + c];
                int gn = h * DH + c;
                *(uint32_t*)(reps + (size_t)(rowbase + r) * DIM + gn) =
                    pack2h(avacc[mf][nt][0] + o0.x, avacc[mf][nt][1] + o0.y);
                *(uint32_t*)(reps + (size_t)(rowbase + r + 8) * DIM + gn) =
                    pack2h(avacc[mf][nt][2] + o1.x, avacc[mf][nt][3] + o1.y);
            }
    }
}

// ---------------------------------------------------------------------------
extern "C" void kernel_launch(void* const* d_in, const int* in_sizes, int n_in,
                              void* d_out, int out_size)
{
    const float* xq = (const float*)d_in[0];
    const float* xk = (const float*)d_in[1];
    const float* xv = (const float*)d_in[2];
    const float* Wq = (const float*)d_in[3];
    const float* bq = (const float*)d_in[4];
    const float* Wk = (const float*)d_in[5];
    const float* bk = (const float*)d_in[6];
    const float* Wv = (const float*)d_in[7];
    const float* bv = (const float*)d_in[8];
    const float* Wo = (const float*)d_in[9];
    const float* bo = (const float*)d_in[10];

    float* pd;
    __half *act, *w, *qh, *kh, *vh, *rh;
    cudaGetSymbolAddress((void**)&pd, g_dummy);
    cudaGetSymbolAddress((void**)&act, g_act);
    cudaGetSymbolAddress((void**)&w, g_w);
    cudaGetSymbolAddress((void**)&qh, g_qh);
    cudaGetSymbolAddress((void**)&kh, g_kh);
    cudaGetSymbolAddress((void**)&vh, g_vh);
    cudaGetSymbolAddress((void**)&rh, g_rh);

    const size_t OUT_ELEMS = (size_t)ROWS_TOT * DIM;
    const size_t ATT_ELEMS = (size_t)BB * NH * SS * SS;

    float* out_ptr = (float*)d_out;
    float* attn_ptr = (float*)d_out + OUT_ELEMS;
    size_t osz = (size_t)out_size;
    if (osz == ATT_ELEMS) {
        attn_ptr = (float*)d_out;
        out_ptr = pd;
    }

    cudaFuncSetAttribute(tc_gemm_qkv, cudaFuncAttributeMaxDynamicSharedMemorySize,
                         TC_SMEM_BYTES);
    cudaFuncSetAttribute(tc_gemm_out, cudaFuncAttributeMaxDynamicSharedMemorySize,
                         TC_SMEM_BYTES);
    cudaFuncSetAttribute(attn_fused, cudaFuncAttributeMaxDynamicSharedMemorySize,
                         FUS_SMEM);

    const int ACT4 = ROWS_TOT * DIM / 4;
    const int W4   = DIM * DIM / 4;

    cvt3<<<dim3((ACT4 + 255) / 256, 1, 3), 256>>>(xq, xk, xv, act, ACT4);
    cvt4<<<dim3((W4 + 255) / 256, 1, 4), 256>>>(Wq, Wk, Wv, Wo, w, W4);

    QkvArgs qa;
    qa.bias[0] = bq; qa.bias[1] = bk; qa.bias[2] = bv;
    qa.C[0] = qh; qa.C[1] = kh; qa.C[2] = vh;
    tc_gemm_qkv<<<dim3(DIM / 128, ROWS_TOT / 128, 3), 256, TC_SMEM_BYTES>>>(
        act, w, qa, ROWS_TOT, DIM, DIM);

    attn_fused<<<dim3(SS / QROWS, BB * NH), 128, FUS_SMEM>>>(
        qh, kh, vh, attn_ptr, rh);

    tc_gemm_out<<<dim3(DIM / 128, ROWS_TOT / 128), 256, TC_SMEM_BYTES>>>(
        rh, w + (size_t)3 * DIM * DIM, bo, out_ptr, ROWS_TOT, DIM, DIM);
}